// round 1
// baseline (speedup 1.0000x reference)
#include <cuda_runtime.h>

// Problem constants (B=2, S=2048, E=2048, H=16, O=1024, A=128)
#define EDIM 2048
#define TM   128          // tokens per block
#define TNC  64           // options per smem chunk
#define KD   128          // A (dot length)
#define OD   1024         // options (codebook size)
#define NCH  (OD / TNC)   // 16 chunks
#define XS_STRIDE 66      // u64 per k-row of Xs2 (64 token-pairs + pad)
#define WS_STRIDE 65      // floats per k-row of Ws (64 opts + pad)
#define SMEM_BYTES (KD*XS_STRIDE*8 + KD*WS_STRIDE*4 + TM*4)

typedef unsigned long long u64;

__device__ __forceinline__ u64 pack2(float lo, float hi) {
    u64 r; asm("mov.b64 %0, {%1, %2};" : "=l"(r) : "f"(lo), "f"(hi)); return r;
}
__device__ __forceinline__ void unpack2(u64 v, float &lo, float &hi) {
    asm("mov.b64 {%0, %1}, %2;" : "=f"(lo), "=f"(hi) : "l"(v));
}
__device__ __forceinline__ u64 ffma2(u64 a, u64 b, u64 c) {
    u64 d; asm("fma.rn.f32x2 %0, %1, %2, %3;" : "=l"(d) : "l"(a), "l"(b), "l"(c));
    return d;
}

// One block = 128 tokens x 1 head. Streams all 1024 options in 64-option
// chunks through smem, fp32 (f32x2-packed) dot products, running argmax,
// then gathers codebook rows.
__global__ __launch_bounds__(256, 2) void vq_argmax_gather(
    const float* __restrict__ x,
    const float* __restrict__ w,
    const float* __restrict__ cb,
    float* __restrict__ out)
{
    extern __shared__ char smem_raw[];
    u64*   Xs2  = (u64*)smem_raw;                                    // [KD][XS_STRIDE]
    float* Ws   = (float*)(smem_raw + KD*XS_STRIDE*8);               // [KD][WS_STRIDE]
    int*   idxs = (int*)(smem_raw + KD*XS_STRIDE*8 + KD*WS_STRIDE*4);// [TM]

    const int tid = threadIdx.x;
    const int tx  = tid & 15;     // option group
    const int ty  = tid >> 4;     // token group (8 tokens each)
    const int t0  = blockIdx.x * TM;
    const int h   = blockIdx.y;

    // ---- Load X tile: tokens [t0,t0+128), k in [0,128), packed as token pairs ----
    {
        const float* xg = x + (size_t)t0 * EDIM + h * KD;
        for (int q = tid; q < (TM/2) * (KD/4); q += 256) {
            int t2 = q >> 5;        // token pair 0..63
            int k4 = q & 31;        // 0..31
            const float4 a = *(const float4*)(xg + (size_t)(2*t2    ) * EDIM + 4*k4);
            const float4 b = *(const float4*)(xg + (size_t)(2*t2 + 1) * EDIM + 4*k4);
            Xs2[(4*k4+0)*XS_STRIDE + t2] = pack2(a.x, b.x);
            Xs2[(4*k4+1)*XS_STRIDE + t2] = pack2(a.y, b.y);
            Xs2[(4*k4+2)*XS_STRIDE + t2] = pack2(a.z, b.z);
            Xs2[(4*k4+3)*XS_STRIDE + t2] = pack2(a.w, b.w);
        }
    }

    float bestv[8];
    int   besti[8];
#pragma unroll
    for (int i = 0; i < 8; i++) { bestv[i] = -3.402823466e38f; besti[i] = 0; }

    const float* wg = w + (size_t)h * OD * KD;

    for (int c = 0; c < NCH; c++) {
        __syncthreads();   // previous chunk fully consumed (and Xs2 ready on c==0)
        // ---- Load W chunk [c*64 .. c*64+64) into Ws[k][o] ----
        const float* wgc = wg + (size_t)c * TNC * KD;
        for (int q = tid; q < TNC * (KD/4); q += 256) {
            int o  = q >> 5;        // 0..63
            int k4 = q & 31;        // 0..31
            const float4 v = *(const float4*)(wgc + (size_t)o * KD + 4*k4);
            Ws[(4*k4+0)*WS_STRIDE + o] = v.x;
            Ws[(4*k4+1)*WS_STRIDE + o] = v.y;
            Ws[(4*k4+2)*WS_STRIDE + o] = v.z;
            Ws[(4*k4+3)*WS_STRIDE + o] = v.w;
        }
        __syncthreads();

        // ---- 8 tokens (4 packed pairs) x 4 options per thread ----
        u64 acc[4][4];
#pragma unroll
        for (int p = 0; p < 4; p++)
#pragma unroll
            for (int u = 0; u < 4; u++) acc[p][u] = 0ULL;

#pragma unroll 4
        for (int k = 0; k < KD; k++) {
            // x: 4 token pairs (conflict-free: 2 distinct 16B addrs per warp)
            ulonglong2 xa = *(const ulonglong2*)(Xs2 + k*XS_STRIDE + ty*4);
            ulonglong2 xb = *(const ulonglong2*)(Xs2 + k*XS_STRIDE + ty*4 + 2);
            u64 xp0 = xa.x, xp1 = xa.y, xp2 = xb.x, xp3 = xb.y;
            // w: strided options {tx, tx+16, tx+32, tx+48} -> conflict-free LDS.32
            const float* wr = Ws + k*WS_STRIDE + tx;
            u64 wp[4];
            wp[0] = pack2(wr[ 0], wr[ 0]);
            wp[1] = pack2(wr[16], wr[16]);
            wp[2] = pack2(wr[32], wr[32]);
            wp[3] = pack2(wr[48], wr[48]);
#pragma unroll
            for (int u = 0; u < 4; u++) {
                acc[0][u] = ffma2(xp0, wp[u], acc[0][u]);
                acc[1][u] = ffma2(xp1, wp[u], acc[1][u]);
                acc[2][u] = ffma2(xp2, wp[u], acc[2][u]);
                acc[3][u] = ffma2(xp3, wp[u], acc[3][u]);
            }
        }

        // ---- fold chunk logits into running argmax (ascending o keeps first-occurrence ties) ----
#pragma unroll
        for (int u = 0; u < 4; u++) {
            const int o_glob = c * TNC + tx + 16*u;
#pragma unroll
            for (int p = 0; p < 4; p++) {
                float v0, v1; unpack2(acc[p][u], v0, v1);
                if (v0 > bestv[2*p  ]) { bestv[2*p  ] = v0; besti[2*p  ] = o_glob; }
                if (v1 > bestv[2*p+1]) { bestv[2*p+1] = v1; besti[2*p+1] = o_glob; }
            }
        }
    }

    // ---- reduce argmax across the 16 tx lanes (xor-shuffle within 16-lane halves) ----
#pragma unroll
    for (int i = 0; i < 8; i++) {
        float v = bestv[i]; int id = besti[i];
#pragma unroll
        for (int off = 8; off >= 1; off >>= 1) {
            float v2 = __shfl_xor_sync(0xffffffffu, v,  off);
            int   i2 = __shfl_xor_sync(0xffffffffu, id, off);
            if (v2 > v || (v2 == v && i2 < id)) { v = v2; id = i2; }
        }
        if (tx == 0) idxs[ty*8 + i] = id;
    }
    __syncthreads();

    // ---- gather codebook rows: out[t, h*128 : h*128+128] = cb[h, idx[t], :] ----
    const float4* cb4  = (const float4*)cb;
    float4*       out4 = (float4*)out;
    for (int q = tid; q < TM * (KD/4); q += 256) {
        int t = q >> 5;
        int j = q & 31;
        int bi = idxs[t];
        out4[(size_t)(t0 + t) * (EDIM/4) + h * (KD/4) + j] =
            cb4[((size_t)h * OD + (size_t)bi) * (KD/4) + j];
    }
}

extern "C" void kernel_launch(void* const* d_in, const int* in_sizes, int n_in,
                              void* d_out, int out_size) {
    const float* x  = (const float*)d_in[0];  // [B,S,E] fp32
    const float* w  = (const float*)d_in[1];  // [H,O,A] fp32
    const float* cb = (const float*)d_in[2];  // [H,O,A] fp32
    // d_in[3] = temperature: mathematically irrelevant in forward pass.
    float* out = (float*)d_out;

    const int ntok = in_sizes[0] / EDIM;      // B*S = 4096
    cudaFuncSetAttribute(vq_argmax_gather,
                         cudaFuncAttributeMaxDynamicSharedMemorySize, SMEM_BYTES);
    dim3 grid(ntok / TM, 16);
    vq_argmax_gather<<<grid, 256, SMEM_BYTES>>>(x, w, cb, out);
}